// round 7
// baseline (speedup 1.0000x reference)
#include <cuda_runtime.h>
#include <math.h>

#define T_STEPS 1024
#define K_FEAT  512
#define BLOCK   32
#define PF      24   // ring depth in float4 loads: 24 x 512B = 12KB in flight / warp
#define STRIDE4 (K_FEAT / 4)   // float4 elements per time step

// One thread owns FOUR adjacent (batch, feature) scans (float4 lanes).
// 128-bit LDG/STG cut LSU instruction pressure 4x (the R5 residual bind
// hypothesis) while keeping traffic identical and raising per-warp bytes
// in flight. Grid = 256 single-warp blocks -> every SM gets 1-2 blocks.
__global__ void __launch_bounds__(BLOCK) alpha_filter_kernel(
    const float* __restrict__ in,     // [B, T, K]
    const float* __restrict__ init,   // [K]
    const float* __restrict__ tau,    // [K]
    float* __restrict__ out)          // [B, T, K]
{
    const int k4 = (blockIdx.x * BLOCK + threadIdx.x) * 4;  // first of 4 features
    const int b  = blockIdx.y;

    // Per-feature coefficients for the 4 scans (matches reference fp32 math)
    float a00[4], a01[4], a10[4], a11[4], b0[4], b1[4], x0[4], x1[4];
#pragma unroll
    for (int j = 0; j < 4; ++j) {
        const float tc      = fmaxf(tau[k4 + j], 1e-8f);
        const float dt_tau  = 0.001f / tc;
        const float dt_tau2 = dt_tau / tc;
        const float e       = expf(-dt_tau);
        a00[j] = e * (1.0f - dt_tau);
        a01[j] = -e * dt_tau2;
        a10[j] = e * 0.001f;
        a11[j] = e * (1.0f + dt_tau);
        b0[j]  = e * dt_tau2;
        b1[j]  = 1.0f - a11[j];
        x0[j]  = 0.0f;
        x1[j]  = init[k4 + j];
    }

    const size_t base = (size_t)b * T_STEPS * K_FEAT + (size_t)k4;
    const float4* ip = (const float4*)(in  + base);
    float4*       op = (float4*)(out + base);

    // Prologue: fill the prefetch ring with t = 0..PF-1
    float4 buf[PF];
#pragma unroll
    for (int i = 0; i < PF; ++i)
        buf[i] = ip[(size_t)i * STRIDE4];
    ip += (size_t)PF * STRIDE4;

    // Main loop: consume step t, prefetch step t+PF.
    // Steps that still prefetch = T_STEPS - PF = 1000 = 41*24 + 16.
#pragma unroll 1
    for (int done = 0; done + PF <= T_STEPS - PF; done += PF) {
#pragma unroll
        for (int i = 0; i < PF; ++i) {
            const float4 u = buf[i];
            buf[i] = ip[(size_t)i * STRIDE4];   // prefetch t + PF
            float4 o;
            {
                const float nx0 = fmaf(a00[0], x0[0], fmaf(a01[0], x1[0], b0[0] * u.x));
                const float nx1 = fmaf(a10[0], x0[0], fmaf(a11[0], x1[0], b1[0] * u.x));
                x0[0] = nx0; x1[0] = nx1; o.x = nx1;
            }
            {
                const float nx0 = fmaf(a00[1], x0[1], fmaf(a01[1], x1[1], b0[1] * u.y));
                const float nx1 = fmaf(a10[1], x0[1], fmaf(a11[1], x1[1], b1[1] * u.y));
                x0[1] = nx0; x1[1] = nx1; o.y = nx1;
            }
            {
                const float nx0 = fmaf(a00[2], x0[2], fmaf(a01[2], x1[2], b0[2] * u.z));
                const float nx1 = fmaf(a10[2], x0[2], fmaf(a11[2], x1[2], b1[2] * u.z));
                x0[2] = nx0; x1[2] = nx1; o.z = nx1;
            }
            {
                const float nx0 = fmaf(a00[3], x0[3], fmaf(a01[3], x1[3], b0[3] * u.w));
                const float nx1 = fmaf(a10[3], x0[3], fmaf(a11[3], x1[3], b1[3] * u.w));
                x0[3] = nx0; x1[3] = nx1; o.w = nx1;
            }
            __stcs(op + (size_t)i * STRIDE4, o);
        }
        ip += (size_t)PF * STRIDE4;
        op += (size_t)PF * STRIDE4;
    }

    // Partial chunk: remaining steps that still prefetch.
#define REM ((T_STEPS - PF) % PF)
#if REM
#pragma unroll
    for (int i = 0; i < REM; ++i) {
        const float4 u = buf[i];
        buf[i] = ip[(size_t)i * STRIDE4];
        float4 o;
        const float uu[4] = {u.x, u.y, u.z, u.w};
        float oo[4];
#pragma unroll
        for (int j = 0; j < 4; ++j) {
            const float nx0 = fmaf(a00[j], x0[j], fmaf(a01[j], x1[j], b0[j] * uu[j]));
            const float nx1 = fmaf(a10[j], x0[j], fmaf(a11[j], x1[j], b1[j] * uu[j]));
            x0[j] = nx0; x1[j] = nx1; oo[j] = nx1;
        }
        o.x = oo[0]; o.y = oo[1]; o.z = oo[2]; o.w = oo[3];
        __stcs(op + (size_t)i * STRIDE4, o);
    }
    ip += (size_t)REM * STRIDE4;
    op += (size_t)REM * STRIDE4;
#endif

    // Epilogue: drain the last PF buffered inputs (no further prefetch).
    // Ring read order continues from index REM (mod PF).
#pragma unroll
    for (int i = 0; i < PF; ++i) {
        const int idx = (REM + i) % PF;
        const float4 u = buf[idx];
        float4 o;
        const float uu[4] = {u.x, u.y, u.z, u.w};
        float oo[4];
#pragma unroll
        for (int j = 0; j < 4; ++j) {
            const float nx0 = fmaf(a00[j], x0[j], fmaf(a01[j], x1[j], b0[j] * uu[j]));
            const float nx1 = fmaf(a10[j], x0[j], fmaf(a11[j], x1[j], b1[j] * uu[j]));
            x0[j] = nx0; x1[j] = nx1; oo[j] = nx1;
        }
        o.x = oo[0]; o.y = oo[1]; o.z = oo[2]; o.w = oo[3];
        __stcs(op + (size_t)i * STRIDE4, o);
    }
}

extern "C" void kernel_launch(void* const* d_in, const int* in_sizes, int n_in,
                              void* d_out, int out_size) {
    const float* inputs = (const float*)d_in[0];   // [B, T, K]
    const float* init   = (const float*)d_in[1];   // [K]
    const float* tau    = (const float*)d_in[2];   // [K]
    float*       out    = (float*)d_out;

    const int batch = in_sizes[0] / (T_STEPS * K_FEAT);   // 64
    dim3 grid(K_FEAT / 4 / BLOCK, batch);                 // (4, 64) = 256 blocks
    alpha_filter_kernel<<<grid, BLOCK>>>(inputs, init, tau, out);
}

// round 8
// speedup vs baseline: 1.2650x; 1.2650x over previous
#include <cuda_runtime.h>
#include <math.h>

#define T_STEPS 1024
#define K_FEAT  512
#define BLOCK   64
#define PF      32   // ring depth in float2 loads: 32 x 256B = 8KB in flight / warp
#define STRIDE2 (K_FEAT / 2)   // float2 elements per time step

// One thread owns TWO adjacent (batch, feature) scans (float2 lanes).
// 64-bit LDG/STG halve LSU instruction pressure vs scalar (R5's residual
// bind hypothesis) with identical traffic. 512 warps chip-wide (~3.5/SM,
// 28KB in flight/SM) keeps latency coverage; ~110 regs, no spill
// (R6's float4 attempt died to 255-reg spill + 1.7 warps/SM).
// T-PF = 992 = 31*32: ring divides exactly, no modular epilogue.
__global__ void __launch_bounds__(BLOCK) alpha_filter_kernel(
    const float* __restrict__ in,     // [B, T, K]
    const float* __restrict__ init,   // [K]
    const float* __restrict__ tau,    // [K]
    float* __restrict__ out)          // [B, T, K]
{
    const int k2 = (blockIdx.x * BLOCK + threadIdx.x) * 2;  // first of 2 features
    const int b  = blockIdx.y;

    // Per-feature coefficients for the 2 scans (matches reference fp32 math)
    float a00[2], a01[2], a10[2], a11[2], b0[2], b1[2], x0[2], x1[2];
#pragma unroll
    for (int j = 0; j < 2; ++j) {
        const float tc      = fmaxf(tau[k2 + j], 1e-8f);
        const float dt_tau  = 0.001f / tc;
        const float dt_tau2 = dt_tau / tc;
        const float e       = expf(-dt_tau);
        a00[j] = e * (1.0f - dt_tau);
        a01[j] = -e * dt_tau2;
        a10[j] = e * 0.001f;
        a11[j] = e * (1.0f + dt_tau);
        b0[j]  = e * dt_tau2;
        b1[j]  = 1.0f - a11[j];
        x0[j]  = 0.0f;
        x1[j]  = init[k2 + j];
    }

    const size_t base = (size_t)b * T_STEPS * K_FEAT + (size_t)k2;
    const float2* ip = (const float2*)(in  + base);
    float2*       op = (float2*)(out + base);

    // Prologue: fill the prefetch ring with t = 0..PF-1
    float2 buf[PF];
#pragma unroll
    for (int i = 0; i < PF; ++i)
        buf[i] = ip[(size_t)i * STRIDE2];
    ip += (size_t)PF * STRIDE2;

    // Main loop: consume step t, prefetch step t+PF.
    // Steps that still prefetch = T_STEPS - PF = 992 = 31 chunks of 32.
#pragma unroll 1
    for (int blk = 0; blk < (T_STEPS - PF) / PF; ++blk) {
#pragma unroll
        for (int i = 0; i < PF; ++i) {
            const float2 u = buf[i];
            buf[i] = ip[(size_t)i * STRIDE2];   // prefetch t + PF
            float2 o;
            {
                const float nx0 = fmaf(a00[0], x0[0], fmaf(a01[0], x1[0], b0[0] * u.x));
                const float nx1 = fmaf(a10[0], x0[0], fmaf(a11[0], x1[0], b1[0] * u.x));
                x0[0] = nx0; x1[0] = nx1; o.x = nx1;
            }
            {
                const float nx0 = fmaf(a00[1], x0[1], fmaf(a01[1], x1[1], b0[1] * u.y));
                const float nx1 = fmaf(a10[1], x0[1], fmaf(a11[1], x1[1], b1[1] * u.y));
                x0[1] = nx0; x1[1] = nx1; o.y = nx1;
            }
            __stcs(op + (size_t)i * STRIDE2, o);
        }
        ip += (size_t)PF * STRIDE2;
        op += (size_t)PF * STRIDE2;
    }

    // Epilogue: drain the last PF buffered inputs (no further prefetch).
#pragma unroll
    for (int i = 0; i < PF; ++i) {
        const float2 u = buf[i];
        float2 o;
        {
            const float nx0 = fmaf(a00[0], x0[0], fmaf(a01[0], x1[0], b0[0] * u.x));
            const float nx1 = fmaf(a10[0], x0[0], fmaf(a11[0], x1[0], b1[0] * u.x));
            x0[0] = nx0; x1[0] = nx1; o.x = nx1;
        }
        {
            const float nx0 = fmaf(a00[1], x0[1], fmaf(a01[1], x1[1], b0[1] * u.y));
            const float nx1 = fmaf(a10[1], x0[1], fmaf(a11[1], x1[1], b1[1] * u.y));
            x0[1] = nx0; x1[1] = nx1; o.y = nx1;
        }
        __stcs(op + (size_t)i * STRIDE2, o);
    }
}

extern "C" void kernel_launch(void* const* d_in, const int* in_sizes, int n_in,
                              void* d_out, int out_size) {
    const float* inputs = (const float*)d_in[0];   // [B, T, K]
    const float* init   = (const float*)d_in[1];   // [K]
    const float* tau    = (const float*)d_in[2];   // [K]
    float*       out    = (float*)d_out;

    const int batch = in_sizes[0] / (T_STEPS * K_FEAT);   // 64
    dim3 grid(K_FEAT / 2 / BLOCK, batch);                 // (4, 64) = 256 blocks
    alpha_filter_kernel<<<grid, BLOCK>>>(inputs, init, tau, out);
}